// round 7
// baseline (speedup 1.0000x reference)
#include <cuda_runtime.h>
#include <math.h>

#define H 1024
#define S 2048
#define VOCAB 50257
#define VBLK 6283            // ceil(VOCAB*32 / 256) vocab blocks (8 rows each)

// ---------------- scratch (__device__ globals) -----------------------------
__device__ float g_h0[H];
__device__ float g_h1[H];
__device__ float g_energ[S];
__device__ float g_am[256];          // attention (max, expsum) partials
__device__ float g_as[256];
__device__ float g_ctx_part[256 * H];
__device__ float g_ctx[H];
__device__ float g_xout[2 * H];      // [h1, ctx]
__device__ float g_vm[VBLK];         // vocab lse partials (per k_vocab block)
__device__ float g_vs[VBLK];

__device__ __forceinline__ float wred(float v) {
#pragma unroll
    for (int o = 16; o; o >>= 1) v += __shfl_xor_sync(0xffffffffu, v, o);
    return v;
}
__device__ __forceinline__ float sig_(float x) { return 1.0f / (1.0f + expf(-x)); }

// online (max, expsum) merge — deterministic, guards empty partials
__device__ __forceinline__ void msmerge(float& m1, float& s1, float m2, float s2) {
    if (s2 == 0.0f) return;
    if (s1 == 0.0f) { m1 = m2; s1 = s2; return; }
    if (m2 > m1) { float tm = m1; m1 = m2; m2 = tm; float ts = s1; s1 = s2; s2 = ts; }
    s1 += s2 * expf(m2 - m1);
}

// ---------------- fused GRU layer: one BLOCK (256 thr) per output j --------
template <int N, bool GATHER>
__global__ void k_gru(const float* __restrict__ Wih, const float* __restrict__ Whh,
                      const float* __restrict__ bih, const float* __restrict__ bhh,
                      const float* __restrict__ xin,
                      const float* __restrict__ emb, const int* __restrict__ word,
                      const float* __restrict__ lastctx,
                      const float* __restrict__ hprev,
                      float* __restrict__ hout, float* __restrict__ hcopy) {
    __shared__ float smem[6][8];
    int j = blockIdx.x;
    int tid = threadIdx.x;
    int lane = tid & 31, warp = tid >> 5;

    const float4* wr4 = reinterpret_cast<const float4*>(Wih + (size_t)j * N);
    const float4* wz4 = reinterpret_cast<const float4*>(Wih + (size_t)(H + j) * N);
    const float4* wn4 = reinterpret_cast<const float4*>(Wih + (size_t)(2 * H + j) * N);
    const float4* ur4 = reinterpret_cast<const float4*>(Whh + (size_t)j * H);
    const float4* uz4 = reinterpret_cast<const float4*>(Whh + (size_t)(H + j) * H);
    const float4* un4 = reinterpret_cast<const float4*>(Whh + (size_t)(2 * H + j) * H);
    const float4* h4  = reinterpret_cast<const float4*>(hprev);

    float ir = 0.f, iz = 0.f, in_ = 0.f, hr = 0.f, hz = 0.f, hn = 0.f;

    if (GATHER) {
        const float4* e4 = reinterpret_cast<const float4*>(emb) + (size_t)word[0] * (H / 4);
        const float4* c4 = reinterpret_cast<const float4*>(lastctx);
#pragma unroll
        for (int i = tid; i < N / 4; i += 256) {
            float4 xv = (i < H / 4) ? e4[i] : c4[i - H / 4];
            float4 a = wr4[i], b = wz4[i], c = wn4[i];
            ir  += a.x * xv.x + a.y * xv.y + a.z * xv.z + a.w * xv.w;
            iz  += b.x * xv.x + b.y * xv.y + b.z * xv.z + b.w * xv.w;
            in_ += c.x * xv.x + c.y * xv.y + c.z * xv.z + c.w * xv.w;
        }
    } else {
        const float4* x4 = reinterpret_cast<const float4*>(xin);
#pragma unroll
        for (int i = tid; i < N / 4; i += 256) {
            float4 xv = x4[i];
            float4 a = wr4[i], b = wz4[i], c = wn4[i];
            ir  += a.x * xv.x + a.y * xv.y + a.z * xv.z + a.w * xv.w;
            iz  += b.x * xv.x + b.y * xv.y + b.z * xv.z + b.w * xv.w;
            in_ += c.x * xv.x + c.y * xv.y + c.z * xv.z + c.w * xv.w;
        }
    }
    {   // H/4 = 256 float4 -> exactly one iteration per thread
        float4 hv = h4[tid];
        float4 a = ur4[tid], b = uz4[tid], c = un4[tid];
        hr = a.x * hv.x + a.y * hv.y + a.z * hv.z + a.w * hv.w;
        hz = b.x * hv.x + b.y * hv.y + b.z * hv.z + b.w * hv.w;
        hn = c.x * hv.x + c.y * hv.y + c.z * hv.z + c.w * hv.w;
    }
    ir = wred(ir); iz = wred(iz); in_ = wred(in_);
    hr = wred(hr); hz = wred(hz); hn = wred(hn);
    if (lane == 0) {
        smem[0][warp] = ir; smem[1][warp] = iz; smem[2][warp] = in_;
        smem[3][warp] = hr; smem[4][warp] = hz; smem[5][warp] = hn;
    }
    __syncthreads();
    if (tid == 0) {
        float v[6];
#pragma unroll
        for (int g = 0; g < 6; ++g) {
            float s = smem[g][0];
#pragma unroll
            for (int w = 1; w < 8; ++w) s += smem[g][w];
            v[g] = s;
        }
        float r  = sig_((v[0] + bih[j]) + (v[3] + bhh[j]));
        float z  = sig_((v[1] + bih[H + j]) + (v[4] + bhh[H + j]));
        float nn = tanhf((v[2] + bih[2 * H + j]) + r * (v[5] + bhh[2 * H + j]));
        float h  = (1.0f - z) * nn + z * hprev[j];
        hout[j] = h;
        hcopy[j] = h;
    }
}

// ---------------- energies + per-block (m,s) softmax partial ---------------
// 256 blocks x 256 threads; warp per s-row (8 rows/block)
__global__ void k_energy(const float* __restrict__ enc, const float* __restrict__ h1) {
    __shared__ float se[8];
    int lane = threadIdx.x & 31, warp = threadIdx.x >> 5;
    int s = blockIdx.x * 8 + warp;
    const float4* w4 = reinterpret_cast<const float4*>(enc) + (size_t)s * 256;
    const float4* x4 = reinterpret_cast<const float4*>(h1);
    float e = 0.f;
#pragma unroll
    for (int i = lane; i < 256; i += 32) {
        float4 a = w4[i], c = x4[i];
        e += a.x * c.x + a.y * c.y + a.z * c.z + a.w * c.w;
    }
    e = wred(e);
    if (lane == 0) { g_energ[s] = e; se[warp] = e; }
    __syncthreads();
    if (threadIdx.x == 0) {
        float m = se[0];
#pragma unroll
        for (int w = 1; w < 8; ++w) m = fmaxf(m, se[w]);
        float sum = 0.f;
#pragma unroll
        for (int w = 0; w < 8; ++w) sum += expf(se[w] - m);
        g_am[blockIdx.x] = m;
        g_as[blockIdx.x] = sum;
    }
}

// context partial: 256 blocks x 256 threads; 8 s-rows per block, float4 cols.
// Each block recomputes the attention LSE from the 256 (m,s) partials
// (identical deterministic smem tree in every block; L2-hot).
__global__ void k_ctx(const float* __restrict__ enc, float* __restrict__ attn_out) {
    __shared__ float sm[256], ss[256];
    int t = threadIdx.x;
    int s0 = blockIdx.x * 8;
    sm[t] = g_am[t]; ss[t] = g_as[t];
    __syncthreads();
#pragma unroll
    for (int off = 128; off >= 1; off >>= 1) {
        if (t < off) msmerge(sm[t], ss[t], sm[t + off], ss[t + off]);
        __syncthreads();
    }
    float lse = sm[0] + logf(ss[0]);
    float w[8];
#pragma unroll
    for (int r = 0; r < 8; ++r) w[r] = expf(g_energ[s0 + r] - lse);
    if (t < 8) attn_out[s0 + t] = w[t];

    const float4* e4 = reinterpret_cast<const float4*>(enc) + (size_t)s0 * 256;
    float4 acc = make_float4(0.f, 0.f, 0.f, 0.f);
#pragma unroll
    for (int r = 0; r < 8; ++r) {
        float4 v = e4[r * 256 + t];
        acc.x += w[r] * v.x; acc.y += w[r] * v.y;
        acc.z += w[r] * v.z; acc.w += w[r] * v.w;
    }
    reinterpret_cast<float4*>(g_ctx_part + (size_t)blockIdx.x * H)[t] = acc;
}

// reduce 256 partials -> ctx; warp per 2 output d's, lane-parallel over c.
// 64 blocks x 256 threads; all loads L2-hot, 8 independent loads per lane.
__global__ void k_ctx_reduce(float* __restrict__ ctx_out) {
    int lane = threadIdx.x & 31, warp = threadIdx.x >> 5;
#pragma unroll
    for (int k = 0; k < 2; ++k) {
        int d = blockIdx.x * 16 + warp * 2 + k;
        float acc = 0.f;
#pragma unroll
        for (int i = 0; i < 8; ++i)
            acc += g_ctx_part[(size_t)(lane + 32 * i) * H + d];
        acc = wred(acc);
        if (lane == 0) {
            g_ctx[d] = acc;
            ctx_out[d] = acc;
            g_xout[d] = g_h1[d];
            g_xout[H + d] = acc;
        }
    }
}

// vocab GEMV: warp per row, full 2048 cols, bias fused.
// Each block also emits a (max, expsum) softmax partial over its 8 logits.
__global__ void k_vocab(const float* __restrict__ W, const float* __restrict__ b,
                        float* __restrict__ logits) {
    __shared__ float sm8[8], ss8[8];
    int lane = threadIdx.x & 31, warp = threadIdx.x >> 5;
    int v = blockIdx.x * 8 + warp;
    if (threadIdx.x < 8) { sm8[threadIdx.x] = -INFINITY; ss8[threadIdx.x] = 0.f; }
    __syncthreads();
    if (v < VOCAB) {
        const float4* w4 = reinterpret_cast<const float4*>(W) + (size_t)v * 512;
        const float4* x4 = reinterpret_cast<const float4*>(g_xout);
        float s = 0.f;
#pragma unroll 8
        for (int i = lane; i < 512; i += 32) {
            float4 a = w4[i], c = x4[i];
            s += a.x * c.x + a.y * c.y + a.z * c.z + a.w * c.w;
        }
        s = wred(s);
        if (lane == 0) {
            float lg = s + b[v];
            logits[v] = lg;
            sm8[warp] = lg;
            ss8[warp] = 1.0f;
        }
    }
    __syncthreads();
    if (threadIdx.x == 0) {
        float m = sm8[0], sum = ss8[0];
#pragma unroll
        for (int w = 1; w < 8; ++w) msmerge(m, sum, sm8[w], ss8[w]);
        g_vm[blockIdx.x] = m;
        g_vs[blockIdx.x] = sum;
    }
}

// finalize: each block redundantly reduces the VBLK (m,s) partials (L2-hot,
// identical deterministic order in every block), then subtracts the LSE.
__global__ void k_finalize(float* __restrict__ logits) {
    __shared__ float sm[256], ss[256];
    int t = threadIdx.x;
    float m = -INFINITY, s = 0.f;
    for (int i = t; i < VBLK; i += 256)
        msmerge(m, s, g_vm[i], g_vs[i]);
    sm[t] = m; ss[t] = s;
    __syncthreads();
#pragma unroll
    for (int off = 128; off >= 1; off >>= 1) {
        if (t < off) msmerge(sm[t], ss[t], sm[t + off], ss[t + off]);
        __syncthreads();
    }
    float lse = sm[0] + logf(ss[0]);
    int v = blockIdx.x * blockDim.x + t;
    if (v < VOCAB) logits[v] -= lse;
}

// ---------------- launch ---------------------------------------------------

extern "C" void kernel_launch(void* const* d_in, const int* in_sizes, int n_in,
                              void* d_out, int out_size) {
    const int*   word     = (const int*)  d_in[0];
    const float* last_ctx = (const float*)d_in[1];
    const float* last_hid = (const float*)d_in[2];   // (2,1,H)
    const float* enc      = (const float*)d_in[3];   // (S,1,H)
    const float* emb      = (const float*)d_in[4];
    const float* W_ih0    = (const float*)d_in[5];
    const float* W_hh0    = (const float*)d_in[6];
    const float* b_ih0    = (const float*)d_in[7];
    const float* b_hh0    = (const float*)d_in[8];
    const float* W_ih1    = (const float*)d_in[9];
    const float* W_hh1    = (const float*)d_in[10];
    const float* b_ih1    = (const float*)d_in[11];
    const float* b_hh1    = (const float*)d_in[12];
    const float* W_out    = (const float*)d_in[13];
    const float* b_out    = (const float*)d_in[14];

    float* out       = (float*)d_out;
    float* out_logit = out;                  // [0, V)
    float* out_ctx   = out + VOCAB;          // context
    float* out_h0    = out + VOCAB + H;      // hidden[0]
    float* out_h1    = out + VOCAB + 2 * H;  // hidden[1]
    float* out_attn  = out + VOCAB + 3 * H;  // attn weights

    float *ph0, *ph1;
    cudaGetSymbolAddress((void**)&ph0, g_h0);
    cudaGetSymbolAddress((void**)&ph1, g_h1);

    // 1-2) fused GRU layers, block-per-output-element
    k_gru<2048, true><<<H, 256>>>(W_ih0, W_hh0, b_ih0, b_hh0, nullptr,
                                  emb, word, last_ctx, last_hid, ph0, out_h0);
    k_gru<1024, false><<<H, 256>>>(W_ih1, W_hh1, b_ih1, b_hh1, ph0,
                                   nullptr, nullptr, nullptr, last_hid + H, ph1, out_h1);

    // 3-5) attention
    k_energy<<<256, 256>>>(enc, ph1);
    k_ctx<<<256, 256>>>(enc, out_attn);
    k_ctx_reduce<<<64, 256>>>(out_ctx);

    // 6) vocab logits + per-block lse partials (bias fused)
    k_vocab<<<VBLK, 256>>>(W_out, b_out, out_logit);

    // 7) log_softmax finalize (redundant parallel lse)
    k_finalize<<<(VOCAB + 255) / 256, 256>>>(out_logit);
}

// round 8
// speedup vs baseline: 1.2726x; 1.2726x over previous
#include <cuda_runtime.h>
#include <math.h>

#define H 1024
#define S 2048
#define VOCAB 50257

// ---------------- scratch (__device__ globals) -----------------------------
__device__ float g_h0[H];
__device__ float g_h1[H];
__device__ float g_energ[S];
__device__ float g_am[256];          // attention (max, expsum) partials
__device__ float g_as[256];
__device__ float g_ctx_part[256 * H];
__device__ float g_ctx[H];
__device__ float g_xout[2 * H];      // [h1, ctx]
__device__ float g_lm[64];           // logit lse partials
__device__ float g_ls[64];

__device__ __forceinline__ float wred(float v) {
#pragma unroll
    for (int o = 16; o; o >>= 1) v += __shfl_xor_sync(0xffffffffu, v, o);
    return v;
}
__device__ __forceinline__ float sig_(float x) { return 1.0f / (1.0f + expf(-x)); }

// online (max, expsum) merge — deterministic, guards empty partials
__device__ __forceinline__ void msmerge(float& m1, float& s1, float m2, float s2) {
    if (s2 == 0.0f) return;
    if (s1 == 0.0f) { m1 = m2; s1 = s2; return; }
    if (m2 > m1) { float tm = m1; m1 = m2; m2 = tm; float ts = s1; s1 = s2; s2 = ts; }
    s1 += s2 * expf(m2 - m1);
}

// ---------------- fused GRU layer: one BLOCK (256 thr) per output j --------
template <int N, bool GATHER>
__global__ void k_gru(const float* __restrict__ Wih, const float* __restrict__ Whh,
                      const float* __restrict__ bih, const float* __restrict__ bhh,
                      const float* __restrict__ xin,
                      const float* __restrict__ emb, const int* __restrict__ word,
                      const float* __restrict__ lastctx,
                      const float* __restrict__ hprev,
                      float* __restrict__ hout, float* __restrict__ hcopy) {
    __shared__ float smem[6][8];
    int j = blockIdx.x;
    int tid = threadIdx.x;
    int lane = tid & 31, warp = tid >> 5;

    const float4* wr4 = reinterpret_cast<const float4*>(Wih + (size_t)j * N);
    const float4* wz4 = reinterpret_cast<const float4*>(Wih + (size_t)(H + j) * N);
    const float4* wn4 = reinterpret_cast<const float4*>(Wih + (size_t)(2 * H + j) * N);
    const float4* ur4 = reinterpret_cast<const float4*>(Whh + (size_t)j * H);
    const float4* uz4 = reinterpret_cast<const float4*>(Whh + (size_t)(H + j) * H);
    const float4* un4 = reinterpret_cast<const float4*>(Whh + (size_t)(2 * H + j) * H);
    const float4* h4  = reinterpret_cast<const float4*>(hprev);

    float ir = 0.f, iz = 0.f, in_ = 0.f, hr = 0.f, hz = 0.f, hn = 0.f;

    if (GATHER) {
        const float4* e4 = reinterpret_cast<const float4*>(emb) + (size_t)word[0] * (H / 4);
        const float4* c4 = reinterpret_cast<const float4*>(lastctx);
#pragma unroll
        for (int i = tid; i < N / 4; i += 256) {
            float4 xv = (i < H / 4) ? e4[i] : c4[i - H / 4];
            float4 a = wr4[i], b = wz4[i], c = wn4[i];
            ir  += a.x * xv.x + a.y * xv.y + a.z * xv.z + a.w * xv.w;
            iz  += b.x * xv.x + b.y * xv.y + b.z * xv.z + b.w * xv.w;
            in_ += c.x * xv.x + c.y * xv.y + c.z * xv.z + c.w * xv.w;
        }
    } else {
        const float4* x4 = reinterpret_cast<const float4*>(xin);
#pragma unroll
        for (int i = tid; i < N / 4; i += 256) {
            float4 xv = x4[i];
            float4 a = wr4[i], b = wz4[i], c = wn4[i];
            ir  += a.x * xv.x + a.y * xv.y + a.z * xv.z + a.w * xv.w;
            iz  += b.x * xv.x + b.y * xv.y + b.z * xv.z + b.w * xv.w;
            in_ += c.x * xv.x + c.y * xv.y + c.z * xv.z + c.w * xv.w;
        }
    }
    {   // H/4 = 256 float4 -> exactly one iteration per thread
        float4 hv = h4[tid];
        float4 a = ur4[tid], b = uz4[tid], c = un4[tid];
        hr = a.x * hv.x + a.y * hv.y + a.z * hv.z + a.w * hv.w;
        hz = b.x * hv.x + b.y * hv.y + b.z * hv.z + b.w * hv.w;
        hn = c.x * hv.x + c.y * hv.y + c.z * hv.z + c.w * hv.w;
    }
    ir = wred(ir); iz = wred(iz); in_ = wred(in_);
    hr = wred(hr); hz = wred(hz); hn = wred(hn);
    if (lane == 0) {
        smem[0][warp] = ir; smem[1][warp] = iz; smem[2][warp] = in_;
        smem[3][warp] = hr; smem[4][warp] = hz; smem[5][warp] = hn;
    }
    __syncthreads();
    if (tid == 0) {
        float v[6];
#pragma unroll
        for (int g = 0; g < 6; ++g) {
            float s = smem[g][0];
#pragma unroll
            for (int w = 1; w < 8; ++w) s += smem[g][w];
            v[g] = s;
        }
        float r  = sig_((v[0] + bih[j]) + (v[3] + bhh[j]));
        float z  = sig_((v[1] + bih[H + j]) + (v[4] + bhh[H + j]));
        float nn = tanhf((v[2] + bih[2 * H + j]) + r * (v[5] + bhh[2 * H + j]));
        float h  = (1.0f - z) * nn + z * hprev[j];
        hout[j] = h;
        hcopy[j] = h;
    }
}

// ---------------- energies + per-block (m,s) softmax partial ---------------
// 256 blocks x 256 threads; warp per s-row (8 rows/block)
__global__ void k_energy(const float* __restrict__ enc, const float* __restrict__ h1) {
    __shared__ float se[8];
    int lane = threadIdx.x & 31, warp = threadIdx.x >> 5;
    int s = blockIdx.x * 8 + warp;
    const float4* w4 = reinterpret_cast<const float4*>(enc) + (size_t)s * 256;
    const float4* x4 = reinterpret_cast<const float4*>(h1);
    float e = 0.f;
#pragma unroll
    for (int i = lane; i < 256; i += 32) {
        float4 a = w4[i], c = x4[i];
        e += a.x * c.x + a.y * c.y + a.z * c.z + a.w * c.w;
    }
    e = wred(e);
    if (lane == 0) { g_energ[s] = e; se[warp] = e; }
    __syncthreads();
    if (threadIdx.x == 0) {
        float m = se[0];
#pragma unroll
        for (int w = 1; w < 8; ++w) m = fmaxf(m, se[w]);
        float sum = 0.f;
#pragma unroll
        for (int w = 0; w < 8; ++w) sum += expf(se[w] - m);
        g_am[blockIdx.x] = m;
        g_as[blockIdx.x] = sum;
    }
}

// context partial: 256 blocks x 256 threads; 8 s-rows per block, float4 cols.
// Each block recomputes the attention LSE from the 256 (m,s) partials
// (identical deterministic smem tree in every block; L2-hot).
__global__ void k_ctx(const float* __restrict__ enc, float* __restrict__ attn_out) {
    __shared__ float sm[256], ss[256];
    int t = threadIdx.x;
    int s0 = blockIdx.x * 8;
    sm[t] = g_am[t]; ss[t] = g_as[t];
    __syncthreads();
#pragma unroll
    for (int off = 128; off >= 1; off >>= 1) {
        if (t < off) msmerge(sm[t], ss[t], sm[t + off], ss[t + off]);
        __syncthreads();
    }
    float lse = sm[0] + logf(ss[0]);
    float w[8];
#pragma unroll
    for (int r = 0; r < 8; ++r) w[r] = expf(g_energ[s0 + r] - lse);
    if (t < 8) attn_out[s0 + t] = w[t];

    const float4* e4 = reinterpret_cast<const float4*>(enc) + (size_t)s0 * 256;
    float4 acc = make_float4(0.f, 0.f, 0.f, 0.f);
#pragma unroll
    for (int r = 0; r < 8; ++r) {
        float4 v = e4[r * 256 + t];
        acc.x += w[r] * v.x; acc.y += w[r] * v.y;
        acc.z += w[r] * v.z; acc.w += w[r] * v.w;
    }
    reinterpret_cast<float4*>(g_ctx_part + (size_t)blockIdx.x * H)[t] = acc;
}

// reduce 256 partials -> ctx; warp per 2 output d's, lane-parallel over c.
// 64 blocks x 256 threads; all loads L2-hot, 8 independent loads per lane.
__global__ void k_ctx_reduce(float* __restrict__ ctx_out) {
    int lane = threadIdx.x & 31, warp = threadIdx.x >> 5;
#pragma unroll
    for (int k = 0; k < 2; ++k) {
        int d = blockIdx.x * 16 + warp * 2 + k;
        float acc = 0.f;
#pragma unroll
        for (int i = 0; i < 8; ++i)
            acc += g_ctx_part[(size_t)(lane + 32 * i) * H + d];
        acc = wred(acc);
        if (lane == 0) {
            g_ctx[d] = acc;
            ctx_out[d] = acc;
            g_xout[d] = g_h1[d];
            g_xout[H + d] = acc;
        }
    }
}

// vocab GEMV: warp per row, full 2048 cols, bias fused (R5 plain version)
__global__ void k_vocab(const float* __restrict__ W, const float* __restrict__ b,
                        float* __restrict__ logits) {
    int v = (blockIdx.x * blockDim.x + threadIdx.x) >> 5;
    int lane = threadIdx.x & 31;
    if (v >= VOCAB) return;
    const float4* w4 = reinterpret_cast<const float4*>(W) + (size_t)v * 512;
    const float4* x4 = reinterpret_cast<const float4*>(g_xout);
    float s = 0.f;
#pragma unroll 8
    for (int i = lane; i < 512; i += 32) {
        float4 a = w4[i], c = x4[i];
        s += a.x * c.x + a.y * c.y + a.z * c.z + a.w * c.w;
    }
    s = wred(s);
    if (lane == 0) logits[v] = s + b[v];
}

// logit lse stage 1: 64 blocks x 256 threads, online (m,s) per block
__global__ void k_lse1(const float* __restrict__ logits) {
    __shared__ float sm[8], ss[8];
    const int CH = 786;
    int b = blockIdx.x;
    int lo = b * CH;
    int hi = min(lo + CH, VOCAB);
    int lane = threadIdx.x & 31, warp = threadIdx.x >> 5;
    float m = -INFINITY, s = 0.f;
    for (int v = lo + threadIdx.x; v < hi; v += 256) {
        float x = logits[v];
        if (x > m) { s = s * expf(m - x) + 1.0f; m = x; }
        else s += expf(x - m);
    }
#pragma unroll
    for (int o = 16; o; o >>= 1) {
        float m2 = __shfl_xor_sync(0xffffffffu, m, o);
        float s2 = __shfl_xor_sync(0xffffffffu, s, o);
        msmerge(m, s, m2, s2);
    }
    if (lane == 0) { sm[warp] = m; ss[warp] = s; }
    __syncthreads();
    if (threadIdx.x == 0) {
        float M = sm[0], Ssum = ss[0];
#pragma unroll
        for (int w = 1; w < 8; ++w) msmerge(M, Ssum, sm[w], ss[w]);
        g_lm[b] = M; g_ls[b] = Ssum;
    }
}

// finalize: each block recomputes the final LSE from 64 partials (L2-hot),
// then subtracts. Deterministic identical tree in every block.
__global__ void k_finalize(float* __restrict__ logits) {
    __shared__ float sm[64], ss[64];
    int t = threadIdx.x;
    if (t < 64) { sm[t] = g_lm[t]; ss[t] = g_ls[t]; }
    __syncthreads();
#pragma unroll
    for (int off = 32; off >= 1; off >>= 1) {
        if (t < off) msmerge(sm[t], ss[t], sm[t + off], ss[t + off]);
        __syncthreads();
    }
    float lse = sm[0] + logf(ss[0]);
    int v = blockIdx.x * blockDim.x + t;
    if (v < VOCAB) logits[v] -= lse;
}

// ---------------- launch ---------------------------------------------------

extern "C" void kernel_launch(void* const* d_in, const int* in_sizes, int n_in,
                              void* d_out, int out_size) {
    const int*   word     = (const int*)  d_in[0];
    const float* last_ctx = (const float*)d_in[1];
    const float* last_hid = (const float*)d_in[2];   // (2,1,H)
    const float* enc      = (const float*)d_in[3];   // (S,1,H)
    const float* emb      = (const float*)d_in[4];
    const float* W_ih0    = (const float*)d_in[5];
    const float* W_hh0    = (const float*)d_in[6];
    const float* b_ih0    = (const float*)d_in[7];
    const float* b_hh0    = (const float*)d_in[8];
    const float* W_ih1    = (const float*)d_in[9];
    const float* W_hh1    = (const float*)d_in[10];
    const float* b_ih1    = (const float*)d_in[11];
    const float* b_hh1    = (const float*)d_in[12];
    const float* W_out    = (const float*)d_in[13];
    const float* b_out    = (const float*)d_in[14];

    float* out       = (float*)d_out;
    float* out_logit = out;                  // [0, V)
    float* out_ctx   = out + VOCAB;          // context
    float* out_h0    = out + VOCAB + H;      // hidden[0]
    float* out_h1    = out + VOCAB + 2 * H;  // hidden[1]
    float* out_attn  = out + VOCAB + 3 * H;  // attn weights

    float *ph0, *ph1;
    cudaGetSymbolAddress((void**)&ph0, g_h0);
    cudaGetSymbolAddress((void**)&ph1, g_h1);

    // 1-2) fused GRU layers, block-per-output-element
    k_gru<2048, true><<<H, 256>>>(W_ih0, W_hh0, b_ih0, b_hh0, nullptr,
                                  emb, word, last_ctx, last_hid, ph0, out_h0);
    k_gru<1024, false><<<H, 256>>>(W_ih1, W_hh1, b_ih1, b_hh1, ph0,
                                   nullptr, nullptr, nullptr, last_hid + H, ph1, out_h1);

    // 3-5) attention
    k_energy<<<256, 256>>>(enc, ph1);
    k_ctx<<<256, 256>>>(enc, out_attn);
    k_ctx_reduce<<<64, 256>>>(out_ctx);

    // 6) vocab logits (bias fused)
    k_vocab<<<(VOCAB * 32 + 255) / 256, 256>>>(W_out, b_out, out_logit);

    // 7-8) log_softmax
    k_lse1<<<64, 256>>>(out_logit);
    k_finalize<<<(VOCAB + 255) / 256, 256>>>(out_logit);
}

// round 11
// speedup vs baseline: 1.2927x; 1.0159x over previous
#include <cuda_runtime.h>
#include <math.h>

#define H 1024
#define S 2048
#define VOCAB 50257

// ---------------- scratch (__device__ globals) -----------------------------
__device__ float g_h0[H];
__device__ float g_h1[H];
__device__ float g_energ[S];
__device__ float g_am[256];          // attention (max, expsum) partials
__device__ float g_as[256];
__device__ float g_ctx_part[256 * H];
__device__ float g_ctx[H];
__device__ float g_xout[2 * H];      // [h1, ctx]
__device__ float g_lm[64];           // logit lse partials
__device__ float g_ls[64];

__device__ __forceinline__ float wred(float v) {
#pragma unroll
    for (int o = 16; o; o >>= 1) v += __shfl_xor_sync(0xffffffffu, v, o);
    return v;
}
__device__ __forceinline__ float sig_(float x) { return 1.0f / (1.0f + expf(-x)); }

// online (max, expsum) merge — deterministic, guards empty partials
__device__ __forceinline__ void msmerge(float& m1, float& s1, float m2, float s2) {
    if (s2 == 0.0f) return;
    if (s1 == 0.0f) { m1 = m2; s1 = s2; return; }
    if (m2 > m1) { float tm = m1; m1 = m2; m2 = tm; float ts = s1; s1 = s2; s2 = ts; }
    s1 += s2 * expf(m2 - m1);
}

// ---------------- fused GRU layer: one BLOCK (256 thr) per output j --------
template <int N, bool GATHER>
__global__ void k_gru(const float* __restrict__ Wih, const float* __restrict__ Whh,
                      const float* __restrict__ bih, const float* __restrict__ bhh,
                      const float* __restrict__ xin,
                      const float* __restrict__ emb, const int* __restrict__ word,
                      const float* __restrict__ lastctx,
                      const float* __restrict__ hprev,
                      float* __restrict__ hout, float* __restrict__ hcopy) {
    __shared__ float smem[6][8];
    int j = blockIdx.x;
    int tid = threadIdx.x;
    int lane = tid & 31, warp = tid >> 5;

    const float4* wr4 = reinterpret_cast<const float4*>(Wih + (size_t)j * N);
    const float4* wz4 = reinterpret_cast<const float4*>(Wih + (size_t)(H + j) * N);
    const float4* wn4 = reinterpret_cast<const float4*>(Wih + (size_t)(2 * H + j) * N);
    const float4* ur4 = reinterpret_cast<const float4*>(Whh + (size_t)j * H);
    const float4* uz4 = reinterpret_cast<const float4*>(Whh + (size_t)(H + j) * H);
    const float4* un4 = reinterpret_cast<const float4*>(Whh + (size_t)(2 * H + j) * H);
    const float4* h4  = reinterpret_cast<const float4*>(hprev);

    float ir = 0.f, iz = 0.f, in_ = 0.f, hr = 0.f, hz = 0.f, hn = 0.f;

    if (GATHER) {
        const float4* e4 = reinterpret_cast<const float4*>(emb) + (size_t)word[0] * (H / 4);
        const float4* c4 = reinterpret_cast<const float4*>(lastctx);
#pragma unroll
        for (int i = tid; i < N / 4; i += 256) {
            float4 xv = (i < H / 4) ? e4[i] : c4[i - H / 4];
            float4 a = wr4[i], b = wz4[i], c = wn4[i];
            ir  += a.x * xv.x + a.y * xv.y + a.z * xv.z + a.w * xv.w;
            iz  += b.x * xv.x + b.y * xv.y + b.z * xv.z + b.w * xv.w;
            in_ += c.x * xv.x + c.y * xv.y + c.z * xv.z + c.w * xv.w;
        }
    } else {
        const float4* x4 = reinterpret_cast<const float4*>(xin);
#pragma unroll
        for (int i = tid; i < N / 4; i += 256) {
            float4 xv = x4[i];
            float4 a = wr4[i], b = wz4[i], c = wn4[i];
            ir  += a.x * xv.x + a.y * xv.y + a.z * xv.z + a.w * xv.w;
            iz  += b.x * xv.x + b.y * xv.y + b.z * xv.z + b.w * xv.w;
            in_ += c.x * xv.x + c.y * xv.y + c.z * xv.z + c.w * xv.w;
        }
    }
    {   // H/4 = 256 float4 -> exactly one iteration per thread
        float4 hv = h4[tid];
        float4 a = ur4[tid], b = uz4[tid], c = un4[tid];
        hr = a.x * hv.x + a.y * hv.y + a.z * hv.z + a.w * hv.w;
        hz = b.x * hv.x + b.y * hv.y + b.z * hv.z + b.w * hv.w;
        hn = c.x * hv.x + c.y * hv.y + c.z * hv.z + c.w * hv.w;
    }
    ir = wred(ir); iz = wred(iz); in_ = wred(in_);
    hr = wred(hr); hz = wred(hz); hn = wred(hn);
    if (lane == 0) {
        smem[0][warp] = ir; smem[1][warp] = iz; smem[2][warp] = in_;
        smem[3][warp] = hr; smem[4][warp] = hz; smem[5][warp] = hn;
    }
    __syncthreads();
    if (tid == 0) {
        float v[6];
#pragma unroll
        for (int g = 0; g < 6; ++g) {
            float s = smem[g][0];
#pragma unroll
            for (int w = 1; w < 8; ++w) s += smem[g][w];
            v[g] = s;
        }
        float r  = sig_((v[0] + bih[j]) + (v[3] + bhh[j]));
        float z  = sig_((v[1] + bih[H + j]) + (v[4] + bhh[H + j]));
        float nn = tanhf((v[2] + bih[2 * H + j]) + r * (v[5] + bhh[2 * H + j]));
        float h  = (1.0f - z) * nn + z * hprev[j];
        hout[j] = h;
        hcopy[j] = h;
    }
}

// ---------------- energies + block-local softmax + partial context ---------
// 256 blocks x 256 threads; warp per s-row (8 rows/block).
// Keeps enc rows in registers; emits per-block (m, s) and the UNNORMALIZED
// partial context  part_b[d] = sum_{r in b} exp(e_r - m_b) * enc[r][d].
__global__ void k_energy_ctx(const float* __restrict__ enc, const float* __restrict__ h1) {
    __shared__ float se[8];
    __shared__ float sctx[H];               // 4 KB partial-context accumulator
    int tid = threadIdx.x;
    int lane = tid & 31, warp = tid >> 5;
    int s = blockIdx.x * 8 + warp;

    const float4* w4 = reinterpret_cast<const float4*>(enc) + (size_t)s * 256;
    const float4* x4 = reinterpret_cast<const float4*>(h1);

    float4 row[8];                          // this lane's slice of the enc row
    float e = 0.f;
#pragma unroll
    for (int k = 0; k < 8; ++k) {
        float4 a = w4[lane + 32 * k];
        float4 c = x4[lane + 32 * k];
        row[k] = a;
        e += a.x * c.x + a.y * c.y + a.z * c.z + a.w * c.w;
    }
    e = wred(e);
    e = __shfl_sync(0xffffffffu, e, 0);
    if (lane == 0) { g_energ[s] = e; se[warp] = e; }

    // zero the accumulator
    float4* sctx4 = reinterpret_cast<float4*>(sctx);
    sctx4[tid] = make_float4(0.f, 0.f, 0.f, 0.f);
    __syncthreads();

    // block max (all threads read se)
    float m = se[0];
#pragma unroll
    for (int w = 1; w < 8; ++w) m = fmaxf(m, se[w]);
    float wgt = expf(e - m);                // this warp's row weight

    // deterministic warp-ordered accumulation into smem
#pragma unroll
    for (int w = 0; w < 8; ++w) {
        if (warp == w) {
#pragma unroll
            for (int k = 0; k < 8; ++k) {
                int i = lane + 32 * k;
                float4 acc = sctx4[i];
                acc.x += wgt * row[k].x; acc.y += wgt * row[k].y;
                acc.z += wgt * row[k].z; acc.w += wgt * row[k].w;
                sctx4[i] = acc;
            }
        }
        __syncthreads();
    }

    // write partial context + (m, s) partial
    reinterpret_cast<float4*>(g_ctx_part + (size_t)blockIdx.x * H)[tid] = sctx4[tid];
    if (tid == 0) {
        float sum = 0.f;
#pragma unroll
        for (int w = 0; w < 8; ++w) sum += expf(se[w] - m);
        g_am[blockIdx.x] = m;
        g_as[blockIdx.x] = sum;
    }
}

// reduce: global (M, Z) via smem tree, then ctx[d] = sum_b e^{m_b-M} part_b[d] / Z.
// 64 blocks x 256 threads; warp handles 2 d's, lanes parallel over b.
// Also writes normalized attention weights (32 per block).
__global__ void k_ctx_reduce(float* __restrict__ ctx_out, float* __restrict__ attn_out) {
    __shared__ float sm[256], ss[256];
    __shared__ float ssc[256];              // per-partial rescale exp(m_b - M)
    int t = threadIdx.x;
    int lane = t & 31, warp = t >> 5;
    sm[t] = g_am[t]; ss[t] = g_as[t];
    __syncthreads();
    float myM = sm[t];                      // keep own partial for rescale
#pragma unroll
    for (int off = 128; off >= 1; off >>= 1) {
        if (t < off) msmerge(sm[t], ss[t], sm[t + off], ss[t + off]);
        __syncthreads();
    }
    float M = sm[0], Z = ss[0];
    __syncthreads();
    ssc[t] = expf(myM - M);
    __syncthreads();
    float invZ = 1.0f / Z;

    // attention weights: 32 per block
    if (t < 32) {
        int sidx = blockIdx.x * 32 + t;
        attn_out[sidx] = expf(g_energ[sidx] - M) * invZ;
    }

#pragma unroll
    for (int k = 0; k < 2; ++k) {
        int d = blockIdx.x * 16 + warp * 2 + k;
        float acc = 0.f;
#pragma unroll
        for (int i = 0; i < 8; ++i) {
            int b = lane + 32 * i;
            acc += ssc[b] * g_ctx_part[(size_t)b * H + d];
        }
        acc = wred(acc);
        if (lane == 0) {
            float c = acc * invZ;
            g_ctx[d] = c;
            ctx_out[d] = c;
            g_xout[d] = g_h1[d];
            g_xout[H + d] = c;
        }
    }
}

// vocab GEMV: warp per row, full 2048 cols, bias fused (R5 plain version)
__global__ void k_vocab(const float* __restrict__ W, const float* __restrict__ b,
                        float* __restrict__ logits) {
    int v = (blockIdx.x * blockDim.x + threadIdx.x) >> 5;
    int lane = threadIdx.x & 31;
    if (v >= VOCAB) return;
    const float4* w4 = reinterpret_cast<const float4*>(W) + (size_t)v * 512;
    const float4* x4 = reinterpret_cast<const float4*>(g_xout);
    float s = 0.f;
#pragma unroll 8
    for (int i = lane; i < 512; i += 32) {
        float4 a = w4[i], c = x4[i];
        s += a.x * c.x + a.y * c.y + a.z * c.z + a.w * c.w;
    }
    s = wred(s);
    if (lane == 0) logits[v] = s + b[v];
}

// logit lse stage 1: 64 blocks x 256 threads, online (m,s) per block
__global__ void k_lse1(const float* __restrict__ logits) {
    __shared__ float sm[8], ss[8];
    const int CH = 786;
    int b = blockIdx.x;
    int lo = b * CH;
    int hi = min(lo + CH, VOCAB);
    int lane = threadIdx.x & 31, warp = threadIdx.x >> 5;
    float m = -INFINITY, s = 0.f;
    for (int v = lo + threadIdx.x; v < hi; v += 256) {
        float x = logits[v];
        if (x > m) { s = s * expf(m - x) + 1.0f; m = x; }
        else s += expf(x - m);
    }
#pragma unroll
    for (int o = 16; o; o >>= 1) {
        float m2 = __shfl_xor_sync(0xffffffffu, m, o);
        float s2 = __shfl_xor_sync(0xffffffffu, s, o);
        msmerge(m, s, m2, s2);
    }
    if (lane == 0) { sm[warp] = m; ss[warp] = s; }
    __syncthreads();
    if (threadIdx.x == 0) {
        float M = sm[0], Ssum = ss[0];
#pragma unroll
        for (int w = 1; w < 8; ++w) msmerge(M, Ssum, sm[w], ss[w]);
        g_lm[b] = M; g_ls[b] = Ssum;
    }
}

// finalize: each block recomputes the final LSE from 64 partials (L2-hot),
// then subtracts. Deterministic identical tree in every block.
__global__ void k_finalize(float* __restrict__ logits) {
    __shared__ float sm[64], ss[64];
    int t = threadIdx.x;
    if (t < 64) { sm[t] = g_lm[t]; ss[t] = g_ls[t]; }
    __syncthreads();
#pragma unroll
    for (int off = 32; off >= 1; off >>= 1) {
        if (t < off) msmerge(sm[t], ss[t], sm[t + off], ss[t + off]);
        __syncthreads();
    }
    float lse = sm[0] + logf(ss[0]);
    int v = blockIdx.x * blockDim.x + t;
    if (v < VOCAB) logits[v] -= lse;
}

// ---------------- launch ---------------------------------------------------

extern "C" void kernel_launch(void* const* d_in, const int* in_sizes, int n_in,
                              void* d_out, int out_size) {
    const int*   word     = (const int*)  d_in[0];
    const float* last_ctx = (const float*)d_in[1];
    const float* last_hid = (const float*)d_in[2];   // (2,1,H)
    const float* enc      = (const float*)d_in[3];   // (S,1,H)
    const float* emb      = (const float*)d_in[4];
    const float* W_ih0    = (const float*)d_in[5];
    const float* W_hh0    = (const float*)d_in[6];
    const float* b_ih0    = (const float*)d_in[7];
    const float* b_hh0    = (const float*)d_in[8];
    const float* W_ih1    = (const float*)d_in[9];
    const float* W_hh1    = (const float*)d_in[10];
    const float* b_ih1    = (const float*)d_in[11];
    const float* b_hh1    = (const float*)d_in[12];
    const float* W_out    = (const float*)d_in[13];
    const float* b_out    = (const float*)d_in[14];

    float* out       = (float*)d_out;
    float* out_logit = out;                  // [0, V)
    float* out_ctx   = out + VOCAB;          // context
    float* out_h0    = out + VOCAB + H;      // hidden[0]
    float* out_h1    = out + VOCAB + 2 * H;  // hidden[1]
    float* out_attn  = out + VOCAB + 3 * H;  // attn weights

    float *ph0, *ph1;
    cudaGetSymbolAddress((void**)&ph0, g_h0);
    cudaGetSymbolAddress((void**)&ph1, g_h1);

    // 1-2) fused GRU layers, block-per-output-element
    k_gru<2048, true><<<H, 256>>>(W_ih0, W_hh0, b_ih0, b_hh0, nullptr,
                                  emb, word, last_ctx, last_hid, ph0, out_h0);
    k_gru<1024, false><<<H, 256>>>(W_ih1, W_hh1, b_ih1, b_hh1, ph0,
                                   nullptr, nullptr, nullptr, last_hid + H, ph1, out_h1);

    // 3-4) attention: single enc pass + reduce
    k_energy_ctx<<<256, 256>>>(enc, ph1);
    k_ctx_reduce<<<64, 256>>>(out_ctx, out_attn);

    // 5) vocab logits (bias fused)
    k_vocab<<<(VOCAB * 32 + 255) / 256, 256>>>(W_out, b_out, out_logit);

    // 6-7) log_softmax
    k_lse1<<<64, 256>>>(out_logit);
    k_finalize<<<(VOCAB + 255) / 256, 256>>>(out_logit);
}

// round 12
// speedup vs baseline: 1.3166x; 1.0185x over previous
#include <cuda_runtime.h>
#include <math.h>

#define H 1024
#define S 2048
#define VOCAB 50257

// ---------------- scratch (__device__ globals) -----------------------------
__device__ float g_h0[H];
__device__ float g_h1[H];
__device__ float g_energ[S];
__device__ float g_am[256];          // attention (max, expsum) partials
__device__ float g_as[256];
__device__ float g_ctx_part[256 * H];
__device__ float g_ctx[H];
__device__ float g_xout[2 * H];      // [h1, ctx]
__device__ float g_lm[64];           // logit lse partials
__device__ float g_ls[64];

__device__ __forceinline__ float wred(float v) {
#pragma unroll
    for (int o = 16; o; o >>= 1) v += __shfl_xor_sync(0xffffffffu, v, o);
    return v;
}
__device__ __forceinline__ float sig_(float x) { return 1.0f / (1.0f + expf(-x)); }

// online (max, expsum) merge — deterministic, guards empty partials
__device__ __forceinline__ void msmerge(float& m1, float& s1, float m2, float s2) {
    if (s2 == 0.0f) return;
    if (s1 == 0.0f) { m1 = m2; s1 = s2; return; }
    if (m2 > m1) { float tm = m1; m1 = m2; m2 = tm; float ts = s1; s1 = s2; s2 = ts; }
    s1 += s2 * expf(m2 - m1);
}

// ---------------- fused GRU layer: one BLOCK (256 thr) per output j --------
template <int N, bool GATHER>
__global__ void k_gru(const float* __restrict__ Wih, const float* __restrict__ Whh,
                      const float* __restrict__ bih, const float* __restrict__ bhh,
                      const float* __restrict__ xin,
                      const float* __restrict__ emb, const int* __restrict__ word,
                      const float* __restrict__ lastctx,
                      const float* __restrict__ hprev,
                      float* __restrict__ hout, float* __restrict__ hcopy) {
    __shared__ float smem[6][8];
    int j = blockIdx.x;
    int tid = threadIdx.x;
    int lane = tid & 31, warp = tid >> 5;

    const float4* wr4 = reinterpret_cast<const float4*>(Wih + (size_t)j * N);
    const float4* wz4 = reinterpret_cast<const float4*>(Wih + (size_t)(H + j) * N);
    const float4* wn4 = reinterpret_cast<const float4*>(Wih + (size_t)(2 * H + j) * N);
    const float4* ur4 = reinterpret_cast<const float4*>(Whh + (size_t)j * H);
    const float4* uz4 = reinterpret_cast<const float4*>(Whh + (size_t)(H + j) * H);
    const float4* un4 = reinterpret_cast<const float4*>(Whh + (size_t)(2 * H + j) * H);
    const float4* h4  = reinterpret_cast<const float4*>(hprev);

    float ir = 0.f, iz = 0.f, in_ = 0.f, hr = 0.f, hz = 0.f, hn = 0.f;

    if (GATHER) {
        const float4* e4 = reinterpret_cast<const float4*>(emb) + (size_t)word[0] * (H / 4);
        const float4* c4 = reinterpret_cast<const float4*>(lastctx);
#pragma unroll
        for (int i = tid; i < N / 4; i += 256) {
            float4 xv = (i < H / 4) ? e4[i] : c4[i - H / 4];
            float4 a = wr4[i], b = wz4[i], c = wn4[i];
            ir  += a.x * xv.x + a.y * xv.y + a.z * xv.z + a.w * xv.w;
            iz  += b.x * xv.x + b.y * xv.y + b.z * xv.z + b.w * xv.w;
            in_ += c.x * xv.x + c.y * xv.y + c.z * xv.z + c.w * xv.w;
        }
    } else {
        const float4* x4 = reinterpret_cast<const float4*>(xin);
#pragma unroll
        for (int i = tid; i < N / 4; i += 256) {
            float4 xv = x4[i];
            float4 a = wr4[i], b = wz4[i], c = wn4[i];
            ir  += a.x * xv.x + a.y * xv.y + a.z * xv.z + a.w * xv.w;
            iz  += b.x * xv.x + b.y * xv.y + b.z * xv.z + b.w * xv.w;
            in_ += c.x * xv.x + c.y * xv.y + c.z * xv.z + c.w * xv.w;
        }
    }
    {   // H/4 = 256 float4 -> exactly one iteration per thread
        float4 hv = h4[tid];
        float4 a = ur4[tid], b = uz4[tid], c = un4[tid];
        hr = a.x * hv.x + a.y * hv.y + a.z * hv.z + a.w * hv.w;
        hz = b.x * hv.x + b.y * hv.y + b.z * hv.z + b.w * hv.w;
        hn = c.x * hv.x + c.y * hv.y + c.z * hv.z + c.w * hv.w;
    }
    ir = wred(ir); iz = wred(iz); in_ = wred(in_);
    hr = wred(hr); hz = wred(hz); hn = wred(hn);
    if (lane == 0) {
        smem[0][warp] = ir; smem[1][warp] = iz; smem[2][warp] = in_;
        smem[3][warp] = hr; smem[4][warp] = hz; smem[5][warp] = hn;
    }
    __syncthreads();
    if (tid == 0) {
        float v[6];
#pragma unroll
        for (int g = 0; g < 6; ++g) {
            float s = smem[g][0];
#pragma unroll
            for (int w = 1; w < 8; ++w) s += smem[g][w];
            v[g] = s;
        }
        float r  = sig_((v[0] + bih[j]) + (v[3] + bhh[j]));
        float z  = sig_((v[1] + bih[H + j]) + (v[4] + bhh[H + j]));
        float nn = tanhf((v[2] + bih[2 * H + j]) + r * (v[5] + bhh[2 * H + j]));
        float h  = (1.0f - z) * nn + z * hprev[j];
        hout[j] = h;
        hcopy[j] = h;
    }
}

// ---------------- energies + block-local softmax + partial context ---------
// 256 blocks x 256 threads; warp per s-row (8 rows/block).
// Keeps enc rows in registers; emits per-block (m, s) and the UNNORMALIZED
// partial context  part_b[d] = sum_{r in b} exp(e_r - m_b) * enc[r][d].
__global__ void k_energy_ctx(const float* __restrict__ enc, const float* __restrict__ h1) {
    __shared__ float se[8];
    __shared__ float sctx[H];               // 4 KB partial-context accumulator
    int tid = threadIdx.x;
    int lane = tid & 31, warp = tid >> 5;
    int s = blockIdx.x * 8 + warp;

    const float4* w4 = reinterpret_cast<const float4*>(enc) + (size_t)s * 256;
    const float4* x4 = reinterpret_cast<const float4*>(h1);

    float4 row[8];                          // this lane's slice of the enc row
    float e = 0.f;
#pragma unroll
    for (int k = 0; k < 8; ++k) {
        float4 a = w4[lane + 32 * k];
        float4 c = x4[lane + 32 * k];
        row[k] = a;
        e += a.x * c.x + a.y * c.y + a.z * c.z + a.w * c.w;
    }
    e = wred(e);
    e = __shfl_sync(0xffffffffu, e, 0);
    if (lane == 0) { g_energ[s] = e; se[warp] = e; }

    // zero the accumulator
    float4* sctx4 = reinterpret_cast<float4*>(sctx);
    sctx4[tid] = make_float4(0.f, 0.f, 0.f, 0.f);
    __syncthreads();

    // block max (all threads read se)
    float m = se[0];
#pragma unroll
    for (int w = 1; w < 8; ++w) m = fmaxf(m, se[w]);
    float wgt = expf(e - m);                // this warp's row weight

    // deterministic warp-ordered accumulation into smem
#pragma unroll
    for (int w = 0; w < 8; ++w) {
        if (warp == w) {
#pragma unroll
            for (int k = 0; k < 8; ++k) {
                int i = lane + 32 * k;
                float4 acc = sctx4[i];
                acc.x += wgt * row[k].x; acc.y += wgt * row[k].y;
                acc.z += wgt * row[k].z; acc.w += wgt * row[k].w;
                sctx4[i] = acc;
            }
        }
        __syncthreads();
    }

    // write partial context + (m, s) partial
    reinterpret_cast<float4*>(g_ctx_part + (size_t)blockIdx.x * H)[tid] = sctx4[tid];
    if (tid == 0) {
        float sum = 0.f;
#pragma unroll
        for (int w = 0; w < 8; ++w) sum += expf(se[w] - m);
        g_am[blockIdx.x] = m;
        g_as[blockIdx.x] = sum;
    }
}

// reduce: global (M, Z) via smem tree, then ctx[d] = sum_b e^{m_b-M} part_b[d] / Z.
// 32 blocks x 256 threads; block owns 32 consecutive d's.
// Warp w owns partials b in [32w, 32w+32); lane l owns d = base + l.
// Loads are 32-float coalesced sectors; 32 independent L2-hot loads/thread.
__global__ void k_ctx_reduce(float* __restrict__ ctx_out, float* __restrict__ attn_out) {
    __shared__ float sm[256], ss[256];
    __shared__ float ssc[256];              // per-partial rescale exp(m_b - M)
    __shared__ float spart[8][32];          // per-warp partial sums per d
    int t = threadIdx.x;
    int lane = t & 31, warp = t >> 5;
    int dbase = blockIdx.x * 32;

    sm[t] = g_am[t]; ss[t] = g_as[t];
    __syncthreads();
    float myM = sm[t];                      // keep own partial for rescale
#pragma unroll
    for (int off = 128; off >= 1; off >>= 1) {
        if (t < off) msmerge(sm[t], ss[t], sm[t + off], ss[t + off]);
        __syncthreads();
    }
    float M = sm[0], Z = ss[0];
    __syncthreads();
    ssc[t] = expf(myM - M);
    __syncthreads();
    float invZ = 1.0f / Z;

    // attention weights: 64 per block
    if (t < 64) {
        int sidx = blockIdx.x * 64 + t;
        attn_out[sidx] = expf(g_energ[sidx] - M) * invZ;
    }

    // warp w sums its 32 b's for d = dbase + lane (coalesced across lanes)
    float acc = 0.f;
#pragma unroll
    for (int i = 0; i < 32; ++i) {
        int b = warp * 32 + i;
        acc += ssc[b] * g_ctx_part[(size_t)b * H + dbase + lane];
    }
    spart[warp][lane] = acc;
    __syncthreads();

    // warp 0 combines 8 warp-partials per d
    if (warp == 0) {
        float sum = spart[0][lane];
#pragma unroll
        for (int w = 1; w < 8; ++w) sum += spart[w][lane];
        float c = sum * invZ;
        int d = dbase + lane;
        g_ctx[d] = c;
        ctx_out[d] = c;
        g_xout[d] = g_h1[d];
        g_xout[H + d] = c;
    }
}

// vocab GEMV: warp per row, full 2048 cols, bias fused (R5 plain version)
__global__ void k_vocab(const float* __restrict__ W, const float* __restrict__ b,
                        float* __restrict__ logits) {
    int v = (blockIdx.x * blockDim.x + threadIdx.x) >> 5;
    int lane = threadIdx.x & 31;
    if (v >= VOCAB) return;
    const float4* w4 = reinterpret_cast<const float4*>(W) + (size_t)v * 512;
    const float4* x4 = reinterpret_cast<const float4*>(g_xout);
    float s = 0.f;
#pragma unroll 8
    for (int i = lane; i < 512; i += 32) {
        float4 a = w4[i], c = x4[i];
        s += a.x * c.x + a.y * c.y + a.z * c.z + a.w * c.w;
    }
    s = wred(s);
    if (lane == 0) logits[v] = s + b[v];
}

// logit lse stage 1: 64 blocks x 256 threads, online (m,s) per block
__global__ void k_lse1(const float* __restrict__ logits) {
    __shared__ float sm[8], ss[8];
    const int CH = 786;
    int b = blockIdx.x;
    int lo = b * CH;
    int hi = min(lo + CH, VOCAB);
    int lane = threadIdx.x & 31, warp = threadIdx.x >> 5;
    float m = -INFINITY, s = 0.f;
    for (int v = lo + threadIdx.x; v < hi; v += 256) {
        float x = logits[v];
        if (x > m) { s = s * expf(m - x) + 1.0f; m = x; }
        else s += expf(x - m);
    }
#pragma unroll
    for (int o = 16; o; o >>= 1) {
        float m2 = __shfl_xor_sync(0xffffffffu, m, o);
        float s2 = __shfl_xor_sync(0xffffffffu, s, o);
        msmerge(m, s, m2, s2);
    }
    if (lane == 0) { sm[warp] = m; ss[warp] = s; }
    __syncthreads();
    if (threadIdx.x == 0) {
        float M = sm[0], Ssum = ss[0];
#pragma unroll
        for (int w = 1; w < 8; ++w) msmerge(M, Ssum, sm[w], ss[w]);
        g_lm[b] = M; g_ls[b] = Ssum;
    }
}

// finalize: each block recomputes the final LSE from 64 partials (L2-hot),
// then subtracts. Deterministic identical tree in every block.
__global__ void k_finalize(float* __restrict__ logits) {
    __shared__ float sm[64], ss[64];
    int t = threadIdx.x;
    if (t < 64) { sm[t] = g_lm[t]; ss[t] = g_ls[t]; }
    __syncthreads();
#pragma unroll
    for (int off = 32; off >= 1; off >>= 1) {
        if (t < off) msmerge(sm[t], ss[t], sm[t + off], ss[t + off]);
        __syncthreads();
    }
    float lse = sm[0] + logf(ss[0]);
    int v = blockIdx.x * blockDim.x + t;
    if (v < VOCAB) logits[v] -= lse;
}

// ---------------- launch ---------------------------------------------------

extern "C" void kernel_launch(void* const* d_in, const int* in_sizes, int n_in,
                              void* d_out, int out_size) {
    const int*   word     = (const int*)  d_in[0];
    const float* last_ctx = (const float*)d_in[1];
    const float* last_hid = (const float*)d_in[2];   // (2,1,H)
    const float* enc      = (const float*)d_in[3];   // (S,1,H)
    const float* emb      = (const float*)d_in[4];
    const float* W_ih0    = (const float*)d_in[5];
    const float* W_hh0    = (const float*)d_in[6];
    const float* b_ih0    = (const float*)d_in[7];
    const float* b_hh0    = (const float*)d_in[8];
    const float* W_ih1    = (const float*)d_in[9];
    const float* W_hh1    = (const float*)d_in[10];
    const float* b_ih1    = (const float*)d_in[11];
    const float* b_hh1    = (const float*)d_in[12];
    const float* W_out    = (const float*)d_in[13];
    const float* b_out    = (const float*)d_in[14];

    float* out       = (float*)d_out;
    float* out_logit = out;                  // [0, V)
    float* out_ctx   = out + VOCAB;          // context
    float* out_h0    = out + VOCAB + H;      // hidden[0]
    float* out_h1    = out + VOCAB + 2 * H;  // hidden[1]
    float* out_attn  = out + VOCAB + 3 * H;  // attn weights

    float *ph0, *ph1;
    cudaGetSymbolAddress((void**)&ph0, g_h0);
    cudaGetSymbolAddress((void**)&ph1, g_h1);

    // 1-2) fused GRU layers, block-per-output-element
    k_gru<2048, true><<<H, 256>>>(W_ih0, W_hh0, b_ih0, b_hh0, nullptr,
                                  emb, word, last_ctx, last_hid, ph0, out_h0);
    k_gru<1024, false><<<H, 256>>>(W_ih1, W_hh1, b_ih1, b_hh1, ph0,
                                   nullptr, nullptr, nullptr, last_hid + H, ph1, out_h1);

    // 3-4) attention: single enc pass + coalesced reduce
    k_energy_ctx<<<256, 256>>>(enc, ph1);
    k_ctx_reduce<<<32, 256>>>(out_ctx, out_attn);

    // 5) vocab logits (bias fused)
    k_vocab<<<(VOCAB * 32 + 255) / 256, 256>>>(W_out, b_out, out_logit);

    // 6-7) log_softmax
    k_lse1<<<64, 256>>>(out_logit);
    k_finalize<<<(VOCAB + 255) / 256, 256>>>(out_logit);
}

// round 13
// speedup vs baseline: 1.3201x; 1.0026x over previous
#include <cuda_runtime.h>
#include <math.h>

#define H 1024
#define S 2048
#define VOCAB 50257

// ---------------- scratch (__device__ globals) -----------------------------
__device__ float g_h0[H];
__device__ float g_h1[H];
__device__ float g_energ[S];
__device__ float g_am[256];          // attention (max, expsum) partials
__device__ float g_as[256];
__device__ float g_ctx_part[256 * H];
__device__ float g_ctx[H];
__device__ float g_xout[2 * H];      // [h1, ctx]
__device__ float g_lm[64];           // logit lse partials
__device__ float g_ls[64];

__device__ __forceinline__ float wred(float v) {
#pragma unroll
    for (int o = 16; o; o >>= 1) v += __shfl_xor_sync(0xffffffffu, v, o);
    return v;
}
__device__ __forceinline__ float sig_(float x) { return 1.0f / (1.0f + expf(-x)); }

// online (max, expsum) merge — deterministic, guards empty partials
__device__ __forceinline__ void msmerge(float& m1, float& s1, float m2, float s2) {
    if (s2 == 0.0f) return;
    if (s1 == 0.0f) { m1 = m2; s1 = s2; return; }
    if (m2 > m1) { float tm = m1; m1 = m2; m2 = tm; float ts = s1; s1 = s2; s2 = ts; }
    s1 += s2 * expf(m2 - m1);
}

// ---------------- fused GRU layer: one BLOCK (256 thr) per output j --------
template <int N, bool GATHER>
__global__ void k_gru(const float* __restrict__ Wih, const float* __restrict__ Whh,
                      const float* __restrict__ bih, const float* __restrict__ bhh,
                      const float* __restrict__ xin,
                      const float* __restrict__ emb, const int* __restrict__ word,
                      const float* __restrict__ lastctx,
                      const float* __restrict__ hprev,
                      float* __restrict__ hout, float* __restrict__ hcopy) {
    __shared__ float smem[6][8];
    int j = blockIdx.x;
    int tid = threadIdx.x;
    int lane = tid & 31, warp = tid >> 5;

    const float4* wr4 = reinterpret_cast<const float4*>(Wih + (size_t)j * N);
    const float4* wz4 = reinterpret_cast<const float4*>(Wih + (size_t)(H + j) * N);
    const float4* wn4 = reinterpret_cast<const float4*>(Wih + (size_t)(2 * H + j) * N);
    const float4* ur4 = reinterpret_cast<const float4*>(Whh + (size_t)j * H);
    const float4* uz4 = reinterpret_cast<const float4*>(Whh + (size_t)(H + j) * H);
    const float4* un4 = reinterpret_cast<const float4*>(Whh + (size_t)(2 * H + j) * H);
    const float4* h4  = reinterpret_cast<const float4*>(hprev);

    float ir = 0.f, iz = 0.f, in_ = 0.f, hr = 0.f, hz = 0.f, hn = 0.f;

    if (GATHER) {
        const float4* e4 = reinterpret_cast<const float4*>(emb) + (size_t)word[0] * (H / 4);
        const float4* c4 = reinterpret_cast<const float4*>(lastctx);
#pragma unroll
        for (int i = tid; i < N / 4; i += 256) {
            float4 xv = (i < H / 4) ? e4[i] : c4[i - H / 4];
            float4 a = wr4[i], b = wz4[i], c = wn4[i];
            ir  += a.x * xv.x + a.y * xv.y + a.z * xv.z + a.w * xv.w;
            iz  += b.x * xv.x + b.y * xv.y + b.z * xv.z + b.w * xv.w;
            in_ += c.x * xv.x + c.y * xv.y + c.z * xv.z + c.w * xv.w;
        }
    } else {
        const float4* x4 = reinterpret_cast<const float4*>(xin);
#pragma unroll
        for (int i = tid; i < N / 4; i += 256) {
            float4 xv = x4[i];
            float4 a = wr4[i], b = wz4[i], c = wn4[i];
            ir  += a.x * xv.x + a.y * xv.y + a.z * xv.z + a.w * xv.w;
            iz  += b.x * xv.x + b.y * xv.y + b.z * xv.z + b.w * xv.w;
            in_ += c.x * xv.x + c.y * xv.y + c.z * xv.z + c.w * xv.w;
        }
    }
    {   // H/4 = 256 float4 -> exactly one iteration per thread
        float4 hv = h4[tid];
        float4 a = ur4[tid], b = uz4[tid], c = un4[tid];
        hr = a.x * hv.x + a.y * hv.y + a.z * hv.z + a.w * hv.w;
        hz = b.x * hv.x + b.y * hv.y + b.z * hv.z + b.w * hv.w;
        hn = c.x * hv.x + c.y * hv.y + c.z * hv.z + c.w * hv.w;
    }
    ir = wred(ir); iz = wred(iz); in_ = wred(in_);
    hr = wred(hr); hz = wred(hz); hn = wred(hn);
    if (lane == 0) {
        smem[0][warp] = ir; smem[1][warp] = iz; smem[2][warp] = in_;
        smem[3][warp] = hr; smem[4][warp] = hz; smem[5][warp] = hn;
    }
    __syncthreads();
    if (tid == 0) {
        float v[6];
#pragma unroll
        for (int g = 0; g < 6; ++g) {
            float s = smem[g][0];
#pragma unroll
            for (int w = 1; w < 8; ++w) s += smem[g][w];
            v[g] = s;
        }
        float r  = sig_((v[0] + bih[j]) + (v[3] + bhh[j]));
        float z  = sig_((v[1] + bih[H + j]) + (v[4] + bhh[H + j]));
        float nn = tanhf((v[2] + bih[2 * H + j]) + r * (v[5] + bhh[2 * H + j]));
        float h  = (1.0f - z) * nn + z * hprev[j];
        hout[j] = h;
        hcopy[j] = h;
    }
}

// ---------------- energies + block-local softmax + partial context ---------
// 256 blocks x 256 threads; warp per s-row (8 rows/block).
// Keeps enc rows in registers; emits per-block (m, s) and the UNNORMALIZED
// partial context  part_b[d] = sum_{r in b} exp(e_r - m_b) * enc[r][d].
__global__ void k_energy_ctx(const float* __restrict__ enc, const float* __restrict__ h1) {
    __shared__ float se[8];
    __shared__ float sctx[H];               // 4 KB partial-context accumulator
    int tid = threadIdx.x;
    int lane = tid & 31, warp = tid >> 5;
    int s = blockIdx.x * 8 + warp;

    const float4* w4 = reinterpret_cast<const float4*>(enc) + (size_t)s * 256;
    const float4* x4 = reinterpret_cast<const float4*>(h1);

    float4 row[8];                          // this lane's slice of the enc row
    float e = 0.f;
#pragma unroll
    for (int k = 0; k < 8; ++k) {
        float4 a = w4[lane + 32 * k];
        float4 c = x4[lane + 32 * k];
        row[k] = a;
        e += a.x * c.x + a.y * c.y + a.z * c.z + a.w * c.w;
    }
    e = wred(e);
    e = __shfl_sync(0xffffffffu, e, 0);
    if (lane == 0) { g_energ[s] = e; se[warp] = e; }

    // zero the accumulator
    float4* sctx4 = reinterpret_cast<float4*>(sctx);
    sctx4[tid] = make_float4(0.f, 0.f, 0.f, 0.f);
    __syncthreads();

    // block max (all threads read se)
    float m = se[0];
#pragma unroll
    for (int w = 1; w < 8; ++w) m = fmaxf(m, se[w]);
    float wgt = expf(e - m);                // this warp's row weight

    // deterministic warp-ordered accumulation into smem
#pragma unroll
    for (int w = 0; w < 8; ++w) {
        if (warp == w) {
#pragma unroll
            for (int k = 0; k < 8; ++k) {
                int i = lane + 32 * k;
                float4 acc = sctx4[i];
                acc.x += wgt * row[k].x; acc.y += wgt * row[k].y;
                acc.z += wgt * row[k].z; acc.w += wgt * row[k].w;
                sctx4[i] = acc;
            }
        }
        __syncthreads();
    }

    // write partial context + (m, s) partial
    reinterpret_cast<float4*>(g_ctx_part + (size_t)blockIdx.x * H)[tid] = sctx4[tid];
    if (tid == 0) {
        float sum = 0.f;
#pragma unroll
        for (int w = 0; w < 8; ++w) sum += expf(se[w] - m);
        g_am[blockIdx.x] = m;
        g_as[blockIdx.x] = sum;
    }
}

// reduce: global (M, Z) via smem tree, then ctx[d] = sum_b e^{m_b-M} part_b[d] / Z.
// 32 blocks x 1024 threads; block owns 32 consecutive d's.
// Warp w owns partials b in [8w, 8w+8); lane l owns d = base + l.
// Coalesced 32-float sectors; only 8 loads per thread (short latency chain).
__global__ void k_ctx_reduce(float* __restrict__ ctx_out, float* __restrict__ attn_out) {
    __shared__ float sm[256], ss[256];
    __shared__ float ssc[256];              // per-partial rescale exp(m_b - M)
    __shared__ float spart[32][32];         // per-warp partial sums per d
    int t = threadIdx.x;
    int lane = t & 31, warp = t >> 5;
    int dbase = blockIdx.x * 32;

    float myM = 0.f;
    if (t < 256) { sm[t] = g_am[t]; ss[t] = g_as[t]; }
    __syncthreads();
    if (t < 256) myM = sm[t];               // keep own partial for rescale
#pragma unroll
    for (int off = 128; off >= 1; off >>= 1) {
        if (t < off) msmerge(sm[t], ss[t], sm[t + off], ss[t + off]);
        __syncthreads();
    }
    float M = sm[0], Z = ss[0];
    __syncthreads();
    if (t < 256) ssc[t] = expf(myM - M);
    __syncthreads();
    float invZ = 1.0f / Z;

    // attention weights: 64 per block
    if (t < 64) {
        int sidx = blockIdx.x * 64 + t;
        attn_out[sidx] = expf(g_energ[sidx] - M) * invZ;
    }

    // warp w sums its 8 b's for d = dbase + lane (coalesced across lanes)
    float acc = 0.f;
#pragma unroll
    for (int i = 0; i < 8; ++i) {
        int b = warp * 8 + i;
        acc += ssc[b] * g_ctx_part[(size_t)b * H + dbase + lane];
    }
    spart[warp][lane] = acc;
    __syncthreads();

    // warp 0 combines 32 warp-partials per d (conflict-free: lane-major rows)
    if (warp == 0) {
        float sum = spart[0][lane];
#pragma unroll
        for (int w = 1; w < 32; ++w) sum += spart[w][lane];
        float c = sum * invZ;
        int d = dbase + lane;
        g_ctx[d] = c;
        ctx_out[d] = c;
        g_xout[d] = g_h1[d];
        g_xout[H + d] = c;
    }
}

// vocab GEMV: warp per row, full 2048 cols, bias fused (R5 plain version)
__global__ void k_vocab(const float* __restrict__ W, const float* __restrict__ b,
                        float* __restrict__ logits) {
    int v = (blockIdx.x * blockDim.x + threadIdx.x) >> 5;
    int lane = threadIdx.x & 31;
    if (v >= VOCAB) return;
    const float4* w4 = reinterpret_cast<const float4*>(W) + (size_t)v * 512;
    const float4* x4 = reinterpret_cast<const float4*>(g_xout);
    float s = 0.f;
#pragma unroll 8
    for (int i = lane; i < 512; i += 32) {
        float4 a = w4[i], c = x4[i];
        s += a.x * c.x + a.y * c.y + a.z * c.z + a.w * c.w;
    }
    s = wred(s);
    if (lane == 0) logits[v] = s + b[v];
}

// logit lse stage 1: 64 blocks x 256 threads, online (m,s) per block
__global__ void k_lse1(const float* __restrict__ logits) {
    __shared__ float sm[8], ss[8];
    const int CH = 786;
    int b = blockIdx.x;
    int lo = b * CH;
    int hi = min(lo + CH, VOCAB);
    int lane = threadIdx.x & 31, warp = threadIdx.x >> 5;
    float m = -INFINITY, s = 0.f;
    for (int v = lo + threadIdx.x; v < hi; v += 256) {
        float x = logits[v];
        if (x > m) { s = s * expf(m - x) + 1.0f; m = x; }
        else s += expf(x - m);
    }
#pragma unroll
    for (int o = 16; o; o >>= 1) {
        float m2 = __shfl_xor_sync(0xffffffffu, m, o);
        float s2 = __shfl_xor_sync(0xffffffffu, s, o);
        msmerge(m, s, m2, s2);
    }
    if (lane == 0) { sm[warp] = m; ss[warp] = s; }
    __syncthreads();
    if (threadIdx.x == 0) {
        float M = sm[0], Ssum = ss[0];
#pragma unroll
        for (int w = 1; w < 8; ++w) msmerge(M, Ssum, sm[w], ss[w]);
        g_lm[b] = M; g_ls[b] = Ssum;
    }
}

// finalize: each block recomputes the final LSE from 64 partials (L2-hot),
// then subtracts. Deterministic identical tree in every block.
__global__ void k_finalize(float* __restrict__ logits) {
    __shared__ float sm[64], ss[64];
    int t = threadIdx.x;
    if (t < 64) { sm[t] = g_lm[t]; ss[t] = g_ls[t]; }
    __syncthreads();
#pragma unroll
    for (int off = 32; off >= 1; off >>= 1) {
        if (t < off) msmerge(sm[t], ss[t], sm[t + off], ss[t + off]);
        __syncthreads();
    }
    float lse = sm[0] + logf(ss[0]);
    int v = blockIdx.x * blockDim.x + t;
    if (v < VOCAB) logits[v] -= lse;
}

// ---------------- launch ---------------------------------------------------

extern "C" void kernel_launch(void* const* d_in, const int* in_sizes, int n_in,
                              void* d_out, int out_size) {
    const int*   word     = (const int*)  d_in[0];
    const float* last_ctx = (const float*)d_in[1];
    const float* last_hid = (const float*)d_in[2];   // (2,1,H)
    const float* enc      = (const float*)d_in[3];   // (S,1,H)
    const float* emb      = (const float*)d_in[4];
    const float* W_ih0    = (const float*)d_in[5];
    const float* W_hh0    = (const float*)d_in[6];
    const float* b_ih0    = (const float*)d_in[7];
    const float* b_hh0    = (const float*)d_in[8];
    const float* W_ih1    = (const float*)d_in[9];
    const float* W_hh1    = (const float*)d_in[10];
    const float* b_ih1    = (const float*)d_in[11];
    const float* b_hh1    = (const float*)d_in[12];
    const float* W_out    = (const float*)d_in[13];
    const float* b_out    = (const float*)d_in[14];

    float* out       = (float*)d_out;
    float* out_logit = out;                  // [0, V)
    float* out_ctx   = out + VOCAB;          // context
    float* out_h0    = out + VOCAB + H;      // hidden[0]
    float* out_h1    = out + VOCAB + 2 * H;  // hidden[1]
    float* out_attn  = out + VOCAB + 3 * H;  // attn weights

    float *ph0, *ph1;
    cudaGetSymbolAddress((void**)&ph0, g_h0);
    cudaGetSymbolAddress((void**)&ph1, g_h1);

    // 1-2) fused GRU layers, block-per-output-element
    k_gru<2048, true><<<H, 256>>>(W_ih0, W_hh0, b_ih0, b_hh0, nullptr,
                                  emb, word, last_ctx, last_hid, ph0, out_h0);
    k_gru<1024, false><<<H, 256>>>(W_ih1, W_hh1, b_ih1, b_hh1, ph0,
                                   nullptr, nullptr, nullptr, last_hid + H, ph1, out_h1);

    // 3-4) attention: single enc pass + wide coalesced reduce
    k_energy_ctx<<<256, 256>>>(enc, ph1);
    k_ctx_reduce<<<32, 1024>>>(out_ctx, out_attn);

    // 5) vocab logits (bias fused)
    k_vocab<<<(VOCAB * 32 + 255) / 256, 256>>>(W_out, b_out, out_logit);

    // 6-7) log_softmax
    k_lse1<<<64, 256>>>(out_logit);
    k_finalize<<<(VOCAB + 255) / 256, 256>>>(out_logit);
}